// round 4
// baseline (speedup 1.0000x reference)
#include <cuda_runtime.h>

#define B_DIM 2
#define E_DIM 1024
#define C_DIM 128
#define R_REL 32

// 8 MB scratch for the Gram matrices G[b,s,o].
__device__ float g_G[(size_t)B_DIM * E_DIM * E_DIM];

// ---------------------------------------------------------------------------
// Kernel 1: G[b] = X[b] @ X[b]^T  (1024x1024, K=128)
// 128x128 tile per block, 256 threads, 8x8 register tile (split 4+4),
// K staged in chunks of 32 with REGISTER PREFETCH double-buffering:
// the next chunk's global loads are issued before the current FMA loop,
// hiding load latency under 2048 FMAs. 4 iterations, 8 barriers total.
// ---------------------------------------------------------------------------
__global__ __launch_bounds__(256) void gram_kernel(const float* __restrict__ x) {
    const int b    = blockIdx.z;
    const float* X = x + (size_t)b * E_DIM * C_DIM;
    float* Gb      = g_G + (size_t)b * E_DIM * E_DIM;

    const int row0 = blockIdx.y * 128;
    const int col0 = blockIdx.x * 128;
    const int tid  = threadIdx.x;
    const int tx   = tid & 15;
    const int ty   = tid >> 4;

    __shared__ float As[32][132];   // k-major: As[k][row]
    __shared__ float Bs[32][132];   // k-major: Bs[k][col]

    float acc[8][8];
    #pragma unroll
    for (int i = 0; i < 8; i++)
        #pragma unroll
        for (int j = 0; j < 8; j++) acc[i][j] = 0.f;

    // Per chunk: 128 rows x 32 k = 1024 float4 per side; 4 float4/thread/side.
    // Thread tid handles flat indices tid + i*256; rr = flat>>3, kq = (flat&7)*4.
    float4 pa[4], pb[4];
    #pragma unroll
    for (int i = 0; i < 4; i++) {
        int flat = tid + i * 256;
        int rr   = flat >> 3;
        int kq   = (flat & 7) * 4;
        pa[i] = *(const float4*)&X[(size_t)(row0 + rr) * C_DIM + kq];
        pb[i] = *(const float4*)&X[(size_t)(col0 + rr) * C_DIM + kq];
    }

    #pragma unroll
    for (int c = 0; c < 4; c++) {
        // Commit prefetched chunk to SMEM.
        #pragma unroll
        for (int i = 0; i < 4; i++) {
            int flat = tid + i * 256;
            int rr   = flat >> 3;
            int kq   = (flat & 7) * 4;
            As[kq + 0][rr] = pa[i].x; As[kq + 1][rr] = pa[i].y;
            As[kq + 2][rr] = pa[i].z; As[kq + 3][rr] = pa[i].w;
            Bs[kq + 0][rr] = pb[i].x; Bs[kq + 1][rr] = pb[i].y;
            Bs[kq + 2][rr] = pb[i].z; Bs[kq + 3][rr] = pb[i].w;
        }
        __syncthreads();

        // Prefetch next chunk while FMAs run.
        if (c < 3) {
            const int kk = (c + 1) * 32;
            #pragma unroll
            for (int i = 0; i < 4; i++) {
                int flat = tid + i * 256;
                int rr   = flat >> 3;
                int kq   = (flat & 7) * 4;
                pa[i] = *(const float4*)&X[(size_t)(row0 + rr) * C_DIM + kk + kq];
                pb[i] = *(const float4*)&X[(size_t)(col0 + rr) * C_DIM + kk + kq];
            }
        }

        #pragma unroll
        for (int k = 0; k < 32; k++) {
            float4 a0 = *(const float4*)&As[k][ty * 4];
            float4 a1 = *(const float4*)&As[k][64 + ty * 4];
            float4 b0 = *(const float4*)&Bs[k][tx * 4];
            float4 b1 = *(const float4*)&Bs[k][64 + tx * 4];
            float a[8]  = {a0.x, a0.y, a0.z, a0.w, a1.x, a1.y, a1.z, a1.w};
            float bb[8] = {b0.x, b0.y, b0.z, b0.w, b1.x, b1.y, b1.z, b1.w};
            #pragma unroll
            for (int i = 0; i < 8; i++)
                #pragma unroll
                for (int j = 0; j < 8; j++)
                    acc[i][j] = fmaf(a[i], bb[j], acc[i][j]);
        }
        __syncthreads();
    }

    #pragma unroll
    for (int ig = 0; ig < 2; ig++) {
        #pragma unroll
        for (int i = 0; i < 4; i++) {
            int row = row0 + ig * 64 + ty * 4 + i;
            float* dst = &Gb[(size_t)row * E_DIM + col0];
            *(float4*)&dst[tx * 4] =
                make_float4(acc[ig*4+i][0], acc[ig*4+i][1], acc[ig*4+i][2], acc[ig*4+i][3]);
            *(float4*)&dst[64 + tx * 4] =
                make_float4(acc[ig*4+i][4], acc[ig*4+i][5], acc[ig*4+i][6], acc[ig*4+i][7]);
        }
    }
}

// ---------------------------------------------------------------------------
// Kernel 2: out[b,s,r,o] = G[b,s,o] * R[r,s,o]
// One block per s (1024 blocks): G rows loaded ONCE into registers, all 32 r
// handled in 8 chunks of 4 with batched streaming loads (MLP=4, low regs ->
// high occupancy). R read-once (__ldcs), out streamed (__stcs).
// ---------------------------------------------------------------------------
#define RCHUNK 4

__global__ __launch_bounds__(256) void scale_kernel(const float4* __restrict__ Rrel,
                                                    float4* __restrict__ out) {
    const int E4 = E_DIM / 4;                  // 256 float4 per row
    const int s  = blockIdx.x;
    const int t  = threadIdx.x;                // 0..255

    const float4* G = (const float4*)g_G;
    const float4 g0 = __ldg(&G[(size_t)s * E4 + t]);
    const float4 g1 = __ldg(&G[((size_t)E_DIM + s) * E4 + t]);

    const size_t rbase = (size_t)s * E4 + t;           // R[r,s,:] stride r: E*E4... in float4: r*E_DIM*E4
    const size_t obase0 = ((size_t)s * R_REL) * E4 + t;
    const size_t obase1 = (((size_t)E_DIM + s) * R_REL) * E4 + t;

    #pragma unroll
    for (int rc = 0; rc < R_REL; rc += RCHUNK) {
        float4 rv[RCHUNK];
        #pragma unroll
        for (int rr = 0; rr < RCHUNK; rr++)
            rv[rr] = __ldcs(&Rrel[(size_t)(rc + rr) * E_DIM * E4 + rbase]);

        #pragma unroll
        for (int rr = 0; rr < RCHUNK; rr++) {
            const int r = rc + rr;
            float4 o0, o1;
            o0.x = g0.x * rv[rr].x;  o0.y = g0.y * rv[rr].y;
            o0.z = g0.z * rv[rr].z;  o0.w = g0.w * rv[rr].w;
            o1.x = g1.x * rv[rr].x;  o1.y = g1.y * rv[rr].y;
            o1.z = g1.z * rv[rr].z;  o1.w = g1.w * rv[rr].w;
            __stcs(&out[obase0 + (size_t)r * E4], o0);
            __stcs(&out[obase1 + (size_t)r * E4], o1);
        }
    }
}

extern "C" void kernel_launch(void* const* d_in, const int* in_sizes, int n_in,
                              void* d_out, int out_size) {
    const float* x  = (const float*)d_in[0];   // (B, E, C) fp32
    const float* Rr = (const float*)d_in[1];   // (R_REL, E, E) fp32
    float* out      = (float*)d_out;           // (B, E, R_REL, E) fp32

    dim3 ggrid(E_DIM / 128, E_DIM / 128, B_DIM); // 8 x 8 x 2 = 128 blocks
    gram_kernel<<<ggrid, 256>>>(x);

    scale_kernel<<<E_DIM, 256>>>((const float4*)Rr, (float4*)out);

    (void)in_sizes; (void)n_in; (void)out_size;
}

// round 5
// speedup vs baseline: 1.0305x; 1.0305x over previous
#include <cuda_runtime.h>

#define B_DIM 2
#define E_DIM 1024
#define C_DIM 128
#define R_REL 32

// 8 MB scratch for the Gram matrices G[b,s,o].
__device__ float g_G[(size_t)B_DIM * E_DIM * E_DIM];

// ---------------------------------------------------------------------------
// Kernel 1: G[b] = X[b] @ X[b]^T  (1024x1024, K=128)
// 128x128 tile per block, 256 threads, 8x8 register tile (split 4+4 groups).
// K in 16 chunks of 8, DOUBLE-BUFFERED in SMEM: the LDG for chunk c+1 issues
// before the FMA loop over chunk c, hiding global latency under 512 FMAs.
// Small staging (1 float4/side) and a ~8KB inner body keep regs & I$ safe.
// ---------------------------------------------------------------------------
#define KC 8   // k per chunk

__global__ __launch_bounds__(256) void gram_kernel(const float* __restrict__ x) {
    const int b    = blockIdx.z;
    const float* X = x + (size_t)b * E_DIM * C_DIM;
    float* Gb      = g_G + (size_t)b * E_DIM * E_DIM;

    const int row0 = blockIdx.y * 128;
    const int col0 = blockIdx.x * 128;
    const int tid  = threadIdx.x;
    const int tx   = tid & 15;
    const int ty   = tid >> 4;

    __shared__ float As[2][KC][132];   // k-major: As[buf][k][row]
    __shared__ float Bs[2][KC][132];

    float acc[8][8];
    #pragma unroll
    for (int i = 0; i < 8; i++)
        #pragma unroll
        for (int j = 0; j < 8; j++) acc[i][j] = 0.f;

    // Per chunk: 128 rows x 8 k = 256 float4 per side; 1 float4/thread/side.
    const int rr = tid >> 1;          // 0..127
    const int kq = (tid & 1) * 4;     // 0 or 4
    const float* pAsrc = &X[(size_t)(row0 + rr) * C_DIM + kq];
    const float* pBsrc = &X[(size_t)(col0 + rr) * C_DIM + kq];

    // Prologue: chunk 0 -> buf 0.
    float4 pa = *(const float4*)pAsrc;
    float4 pb = *(const float4*)pBsrc;
    {
        As[0][kq + 0][rr] = pa.x; As[0][kq + 1][rr] = pa.y;
        As[0][kq + 2][rr] = pa.z; As[0][kq + 3][rr] = pa.w;
        Bs[0][kq + 0][rr] = pb.x; Bs[0][kq + 1][rr] = pb.y;
        Bs[0][kq + 2][rr] = pb.z; Bs[0][kq + 3][rr] = pb.w;
    }
    __syncthreads();

    const int NCHUNK = C_DIM / KC;    // 16
    #pragma unroll
    for (int c = 0; c < NCHUNK; c++) {
        const int cur = c & 1;
        const int nxt = cur ^ 1;

        // Issue next chunk's global loads early (latency hidden by FMAs below).
        if (c < NCHUNK - 1) {
            pa = *(const float4*)(pAsrc + (c + 1) * KC);
            pb = *(const float4*)(pBsrc + (c + 1) * KC);
        }

        #pragma unroll
        for (int k = 0; k < KC; k++) {
            float4 a0 = *(const float4*)&As[cur][k][ty * 4];
            float4 a1 = *(const float4*)&As[cur][k][64 + ty * 4];
            float4 b0 = *(const float4*)&Bs[cur][k][tx * 4];
            float4 b1 = *(const float4*)&Bs[cur][k][64 + tx * 4];
            float a[8]  = {a0.x, a0.y, a0.z, a0.w, a1.x, a1.y, a1.z, a1.w};
            float bb[8] = {b0.x, b0.y, b0.z, b0.w, b1.x, b1.y, b1.z, b1.w};
            #pragma unroll
            for (int i = 0; i < 8; i++)
                #pragma unroll
                for (int j = 0; j < 8; j++)
                    acc[i][j] = fmaf(a[i], bb[j], acc[i][j]);
        }

        if (c < NCHUNK - 1) {
            // Safe: buf 'nxt' was last read in iteration c-1, separated by the
            // barrier at the end of that iteration.
            As[nxt][kq + 0][rr] = pa.x; As[nxt][kq + 1][rr] = pa.y;
            As[nxt][kq + 2][rr] = pa.z; As[nxt][kq + 3][rr] = pa.w;
            Bs[nxt][kq + 0][rr] = pb.x; Bs[nxt][kq + 1][rr] = pb.y;
            Bs[nxt][kq + 2][rr] = pb.z; Bs[nxt][kq + 3][rr] = pb.w;
            __syncthreads();
        }
    }

    #pragma unroll
    for (int ig = 0; ig < 2; ig++) {
        #pragma unroll
        for (int i = 0; i < 4; i++) {
            int row = row0 + ig * 64 + ty * 4 + i;
            float* dst = &Gb[(size_t)row * E_DIM + col0];
            *(float4*)&dst[tx * 4] =
                make_float4(acc[ig*4+i][0], acc[ig*4+i][1], acc[ig*4+i][2], acc[ig*4+i][3]);
            *(float4*)&dst[64 + tx * 4] =
                make_float4(acc[ig*4+i][4], acc[ig*4+i][5], acc[ig*4+i][6], acc[ig*4+i][7]);
        }
    }
}

// ---------------------------------------------------------------------------
// Kernel 2 (best measured config, 59.9us): out[b,s,r,o] = G[b,s,o] * R[r,s,o]
// One block per (s, 8-r chunk). All 8 R rows preloaded (explicit MLP=8),
// G rows in registers (L2-resident reads), outputs streamed with __stcs.
// ---------------------------------------------------------------------------
#define RCHUNK 8

__global__ __launch_bounds__(256) void scale_kernel(const float4* __restrict__ Rrel,
                                                    float4* __restrict__ out) {
    const int E4  = E_DIM / 4;                 // 256 float4 per row
    const int bid = blockIdx.x;
    const int s   = bid >> 2;                  // / (R_REL/RCHUNK)
    const int rc  = (bid & 3) * RCHUNK;
    const int t   = threadIdx.x;               // 0..255

    const float4* G = (const float4*)g_G;
    float4 g0 = __ldg(&G[(size_t)s * E4 + t]);
    float4 g1 = __ldg(&G[((size_t)E_DIM + s) * E4 + t]);

    // Batch all 8 streaming R loads up-front for maximum MLP.
    float4 rv[RCHUNK];
    #pragma unroll
    for (int rr = 0; rr < RCHUNK; rr++)
        rv[rr] = __ldcs(&Rrel[((size_t)(rc + rr) * E_DIM + s) * E4 + t]);

    #pragma unroll
    for (int rr = 0; rr < RCHUNK; rr++) {
        const int r = rc + rr;
        float4 o0, o1;
        o0.x = g0.x * rv[rr].x;  o0.y = g0.y * rv[rr].y;
        o0.z = g0.z * rv[rr].z;  o0.w = g0.w * rv[rr].w;
        o1.x = g1.x * rv[rr].x;  o1.y = g1.y * rv[rr].y;
        o1.z = g1.z * rv[rr].z;  o1.w = g1.w * rv[rr].w;

        size_t base0 = (((size_t)s) * R_REL + r) * (size_t)E4 + t;
        size_t base1 = (((size_t)E_DIM + s) * R_REL + r) * (size_t)E4 + t;
        __stcs(&out[base0], o0);
        __stcs(&out[base1], o1);
    }
}

extern "C" void kernel_launch(void* const* d_in, const int* in_sizes, int n_in,
                              void* d_out, int out_size) {
    const float* x  = (const float*)d_in[0];   // (B, E, C) fp32
    const float* Rr = (const float*)d_in[1];   // (R_REL, E, E) fp32
    float* out      = (float*)d_out;           // (B, E, R_REL, E) fp32

    dim3 ggrid(E_DIM / 128, E_DIM / 128, B_DIM); // 8 x 8 x 2 = 128 blocks
    gram_kernel<<<ggrid, 256>>>(x);

    scale_kernel<<<E_DIM * (R_REL / RCHUNK), 256>>>((const float4*)Rr, (float4*)out);

    (void)in_sizes; (void)n_in; (void)out_size;
}

// round 7
// speedup vs baseline: 1.1196x; 1.0864x over previous
#include <cuda_runtime.h>
#include <cuda_bf16.h>
#include <cstdint>

#define B_DIM 2
#define E_DIM 1024
#define C_DIM 128
#define R_REL 32

// 8 MB scratch for the Gram matrices G[b,s,o].
__device__ float g_G[(size_t)B_DIM * E_DIM * E_DIM];

// ---------------------------------------------------------------------------
// Kernel 1: G[b] = X[b] @ X[b]^T via split-bf16 tensor-core GEMM.
// x = hi + lo (hi = bf16(x), lo = bf16(x - hi)).  Three accumulation passes:
//   hi@hi^T + lo@hi^T + hi@lo^T   (drops only lo@lo^T ~ 2^-18 relative)
// 64x64 tile per block, 128 threads (4 warps, 2x2 of 32x32 warp tiles),
// ldmatrix.x4 + mma.sync.m16n8k16.bf16, fp32 accumulate.
// ---------------------------------------------------------------------------
#define GSTRIDE 136   // bf16 elements per smem row (128 + 8 pad): conflict-free

__device__ __forceinline__ uint32_t ldsm_addr(const __nv_bfloat16* p) {
    return (uint32_t)__cvta_generic_to_shared(p);
}

__device__ __forceinline__ float lo_part(float v) {
    return v - __bfloat162float(__float2bfloat16(v));
}

__global__ __launch_bounds__(128) void gram_mma_kernel(const float* __restrict__ x) {
    const int b    = blockIdx.z;
    const float* X = x + (size_t)b * E_DIM * C_DIM;
    float* Gb      = g_G + (size_t)b * E_DIM * E_DIM;

    const int row0 = blockIdx.y * 64;
    const int col0 = blockIdx.x * 64;
    const int tid  = threadIdx.x;
    const int lane = tid & 31;
    const int wid  = tid >> 5;
    const int wm   = wid >> 1;       // warp row (0..1) -> 32 rows
    const int wn   = wid & 1;        // warp col (0..1) -> 32 cols

    __shared__ __align__(16) __nv_bfloat16 As[64][GSTRIDE];
    __shared__ __align__(16) __nv_bfloat16 Bs[64][GSTRIDE];

    float acc[2][4][4];              // [m16-tile][n8-tile][c-frag]
    #pragma unroll
    for (int i = 0; i < 2; i++)
        #pragma unroll
        for (int j = 0; j < 4; j++)
            #pragma unroll
            for (int k = 0; k < 4; k++) acc[i][j][k] = 0.f;

    // Fill indexing: thread handles row rr, half of the 128 k-columns.
    const int rr   = tid >> 1;        // 0..63
    const int half = (tid & 1) * 64;  // float column offset

    // Pass c: A uses loA[c] ? lo : hi ; B uses loB[c] ? lo : hi.
    const int loA[3] = {0, 1, 0};
    const int loB[3] = {0, 0, 1};

    #pragma unroll
    for (int chunk = 0; chunk < 3; chunk++) {
        const float4* srcA = (const float4*)&X[(size_t)(row0 + rr) * C_DIM + half];
        const float4* srcB = (const float4*)&X[(size_t)(col0 + rr) * C_DIM + half];
        #pragma unroll
        for (int i = 0; i < 16; i++) {
            float4 wa = srcA[i];
            float4 wb = srcB[i];
            if (loA[chunk]) {
                wa.x = lo_part(wa.x); wa.y = lo_part(wa.y);
                wa.z = lo_part(wa.z); wa.w = lo_part(wa.w);
            }
            if (loB[chunk]) {
                wb.x = lo_part(wb.x); wb.y = lo_part(wb.y);
                wb.z = lo_part(wb.z); wb.w = lo_part(wb.w);
            }
            __nv_bfloat162* dA = (__nv_bfloat162*)&As[rr][half + i * 4];
            __nv_bfloat162* dB = (__nv_bfloat162*)&Bs[rr][half + i * 4];
            dA[0] = __floats2bfloat162_rn(wa.x, wa.y);
            dA[1] = __floats2bfloat162_rn(wa.z, wa.w);
            dB[0] = __floats2bfloat162_rn(wb.x, wb.y);
            dB[1] = __floats2bfloat162_rn(wb.z, wb.w);
        }
        __syncthreads();

        // ---- 8 k16-steps over this chunk ----
        #pragma unroll
        for (int ks = 0; ks < 8; ks++) {
            uint32_t a[2][4];
            #pragma unroll
            for (int mt = 0; mt < 2; mt++) {
                int r = wm * 32 + mt * 16 + ((lane >> 3) & 1) * 8 + (lane & 7);
                int c = ks * 16 + (lane >> 4) * 8;
                uint32_t addr = ldsm_addr(&As[r][c]);
                asm volatile("ldmatrix.sync.aligned.m8n8.x4.shared.b16 {%0,%1,%2,%3}, [%4];"
                             : "=r"(a[mt][0]), "=r"(a[mt][1]), "=r"(a[mt][2]), "=r"(a[mt][3])
                             : "r"(addr));
            }
            uint32_t bf[2][4];
            #pragma unroll
            for (int p = 0; p < 2; p++) {
                int r = wn * 32 + p * 16 + ((lane >> 4) & 1) * 8 + (lane & 7);
                int c = ks * 16 + ((lane >> 3) & 1) * 8;
                uint32_t addr = ldsm_addr(&Bs[r][c]);
                asm volatile("ldmatrix.sync.aligned.m8n8.x4.shared.b16 {%0,%1,%2,%3}, [%4];"
                             : "=r"(bf[p][0]), "=r"(bf[p][1]), "=r"(bf[p][2]), "=r"(bf[p][3])
                             : "r"(addr));
            }
            #pragma unroll
            for (int mt = 0; mt < 2; mt++) {
                #pragma unroll
                for (int nt = 0; nt < 4; nt++) {
                    uint32_t b0 = bf[nt >> 1][(nt & 1) * 2 + 0];
                    uint32_t b1 = bf[nt >> 1][(nt & 1) * 2 + 1];
                    asm volatile(
                        "mma.sync.aligned.m16n8k16.row.col.f32.bf16.bf16.f32 "
                        "{%0,%1,%2,%3}, {%4,%5,%6,%7}, {%8,%9}, {%0,%1,%2,%3};"
                        : "+f"(acc[mt][nt][0]), "+f"(acc[mt][nt][1]),
                          "+f"(acc[mt][nt][2]), "+f"(acc[mt][nt][3])
                        : "r"(a[mt][0]), "r"(a[mt][1]), "r"(a[mt][2]), "r"(a[mt][3]),
                          "r"(b0), "r"(b1));
                }
            }
        }
        __syncthreads();
    }

    // ---- epilogue: write G tile ----
    #pragma unroll
    for (int mt = 0; mt < 2; mt++) {
        #pragma unroll
        for (int nt = 0; nt < 4; nt++) {
            int r = row0 + wm * 32 + mt * 16 + (lane >> 2);
            int c = col0 + wn * 32 + nt * 8 + (lane & 3) * 2;
            float2 v0 = make_float2(acc[mt][nt][0], acc[mt][nt][1]);
            float2 v1 = make_float2(acc[mt][nt][2], acc[mt][nt][3]);
            *(float2*)&Gb[(size_t)r * E_DIM + c]       = v0;
            *(float2*)&Gb[(size_t)(r + 8) * E_DIM + c] = v1;
        }
    }
}

// ---------------------------------------------------------------------------
// Kernel 2 (best measured config, 59.2us): out[b,s,r,o] = G[b,s,o] * R[r,s,o]
// One block per (s, 8-r chunk). All 8 R rows preloaded (explicit MLP=8),
// G rows in registers (L2-resident reads), outputs streamed with __stcs.
// ---------------------------------------------------------------------------
#define RCHUNK 8

__global__ __launch_bounds__(256) void scale_kernel(const float4* __restrict__ Rrel,
                                                    float4* __restrict__ out) {
    const int E4  = E_DIM / 4;                 // 256 float4 per row
    const int bid = blockIdx.x;
    const int s   = bid >> 2;                  // / (R_REL/RCHUNK)
    const int rc  = (bid & 3) * RCHUNK;
    const int t   = threadIdx.x;               // 0..255

    const float4* G = (const float4*)g_G;
    float4 g0 = __ldg(&G[(size_t)s * E4 + t]);
    float4 g1 = __ldg(&G[((size_t)E_DIM + s) * E4 + t]);

    float4 rv[RCHUNK];
    #pragma unroll
    for (int rr = 0; rr < RCHUNK; rr++)
        rv[rr] = __ldcs(&Rrel[((size_t)(rc + rr) * E_DIM + s) * E4 + t]);

    #pragma unroll
    for (int rr = 0; rr < RCHUNK; rr++) {
        const int r = rc + rr;
        float4 o0, o1;
        o0.x = g0.x * rv[rr].x;  o0.y = g0.y * rv[rr].y;
        o0.z = g0.z * rv[rr].z;  o0.w = g0.w * rv[rr].w;
        o1.x = g1.x * rv[rr].x;  o1.y = g1.y * rv[rr].y;
        o1.z = g1.z * rv[rr].z;  o1.w = g1.w * rv[rr].w;

        size_t base0 = (((size_t)s) * R_REL + r) * (size_t)E4 + t;
        size_t base1 = (((size_t)E_DIM + s) * R_REL + r) * (size_t)E4 + t;
        __stcs(&out[base0], o0);
        __stcs(&out[base1], o1);
    }
}

extern "C" void kernel_launch(void* const* d_in, const int* in_sizes, int n_in,
                              void* d_out, int out_size) {
    const float* x  = (const float*)d_in[0];   // (B, E, C) fp32
    const float* Rr = (const float*)d_in[1];   // (R_REL, E, E) fp32
    float* out      = (float*)d_out;           // (B, E, R_REL, E) fp32

    dim3 ggrid(E_DIM / 64, E_DIM / 64, B_DIM); // 16 x 16 x 2 = 512 blocks
    gram_mma_kernel<<<ggrid, 128>>>(x);

    scale_kernel<<<E_DIM * (R_REL / RCHUNK), 256>>>((const float4*)Rr, (float4*)out);

    (void)in_sizes; (void)n_in; (void)out_size;
}